// round 2
// baseline (speedup 1.0000x reference)
#include <cuda_runtime.h>

// Problem constants (fixed by the dataset)
#define K_DIM   4096   // in_features
#define N_DIM   4096   // out_features
#define M_DIM   8192   // 4 * 2048 rows
#define NNZ     262144

// 64 MB scratch for the updated weight (device global: no allocation allowed)
__device__ float g_newW[(size_t)N_DIM * K_DIM];

// ---------------------------------------------------------------------------
// Kernel 1: copy W -> g_newW (vectorized)
// ---------------------------------------------------------------------------
__global__ void copy_weight_kernel(const float* __restrict__ w) {
    size_t i = (size_t)blockIdx.x * blockDim.x + threadIdx.x;
    const size_t n4 = (size_t)N_DIM * K_DIM / 4;
    if (i < n4) {
        reinterpret_cast<float4*>(g_newW)[i] =
            reinterpret_cast<const float4*>(w)[i];
    }
}

// ---------------------------------------------------------------------------
// Kernel 2: scatter shira delta with atomics (duplicates accumulate, matching
// jax .at[].add semantics)
// ---------------------------------------------------------------------------
__global__ void scatter_delta_kernel(const float* __restrict__ sw,
                                     const int* __restrict__ idx) {
    int i = blockIdx.x * blockDim.x + threadIdx.x;
    if (i < NNZ) {
        int r = idx[i];          // rows are idx[0, :]
        int c = idx[NNZ + i];    // cols are idx[1, :]
        atomicAdd(&g_newW[(size_t)r * K_DIM + c], sw[i]);
    }
}

// ---------------------------------------------------------------------------
// Kernel 3: SGEMM  C[M,N] = A[M,K] * B[N,K]^T + bias
// 128x128 block tile, BK=8, 16x16 threads, 8x8 per-thread microtile,
// double-buffered smem with register staging of the next tile.
// ---------------------------------------------------------------------------
#define BM 128
#define BN 128
#define BK 8
#define TM 8
#define TN 8
#define PAD 4   // smem row padding (floats) to avoid bank conflicts

__global__ void __launch_bounds__(256, 2)
sgemm_kernel(const float* __restrict__ A,        // x  [M, K]
             const float* __restrict__ bias,     // [N]
             float* __restrict__ C) {            // [M, N]
    __shared__ float As[2][BK][BM + PAD];
    __shared__ float Bs[2][BK][BN + PAD];

    const float* __restrict__ B = g_newW;        // [N, K]

    const int tid = threadIdx.x;
    const int tx = tid % 16;        // n-direction
    const int ty = tid / 16;        // m-direction

    const int m0 = blockIdx.y * BM;
    const int n0 = blockIdx.x * BN;

    // Loader mapping: 256 threads, each loads one float4 of A and one of B
    // per K-tile. Tile is 128 rows x 8 k.
    const int l_row = tid >> 1;           // 0..127
    const int l_col = (tid & 1) * 4;      // 0 or 4

    const float* a_ptr = A + (size_t)(m0 + l_row) * K_DIM + l_col;
    const float* b_ptr = B + (size_t)(n0 + l_row) * K_DIM + l_col;

    float acc[TM][TN];
#pragma unroll
    for (int i = 0; i < TM; i++)
#pragma unroll
        for (int j = 0; j < TN; j++)
            acc[i][j] = 0.0f;

    const int KT = K_DIM / BK;   // 512 k-tiles

    // ---- preload tile 0 into stage 0 ----
    {
        float4 av = *reinterpret_cast<const float4*>(a_ptr);
        float4 bv = *reinterpret_cast<const float4*>(b_ptr);
        As[0][l_col + 0][l_row] = av.x;
        As[0][l_col + 1][l_row] = av.y;
        As[0][l_col + 2][l_row] = av.z;
        As[0][l_col + 3][l_row] = av.w;
        Bs[0][l_col + 0][l_row] = bv.x;
        Bs[0][l_col + 1][l_row] = bv.y;
        Bs[0][l_col + 2][l_row] = bv.z;
        Bs[0][l_col + 3][l_row] = bv.w;
    }
    __syncthreads();

    int s = 0;
    for (int kt = 0; kt < KT; ++kt) {
        float4 av, bv;
        const bool has_next = (kt + 1 < KT);
        if (has_next) {
            const float* ap = a_ptr + (size_t)(kt + 1) * BK;
            const float* bp = b_ptr + (size_t)(kt + 1) * BK;
            av = *reinterpret_cast<const float4*>(ap);
            bv = *reinterpret_cast<const float4*>(bp);
        }

        // ---- compute on stage s (hides the LDG latency above) ----
#pragma unroll
        for (int k = 0; k < BK; ++k) {
            float a_frag[TM], b_frag[TN];
            float4 a0 = *reinterpret_cast<const float4*>(&As[s][k][ty * TM]);
            float4 a1 = *reinterpret_cast<const float4*>(&As[s][k][ty * TM + 4]);
            float4 b0 = *reinterpret_cast<const float4*>(&Bs[s][k][tx * TN]);
            float4 b1 = *reinterpret_cast<const float4*>(&Bs[s][k][tx * TN + 4]);
            a_frag[0] = a0.x; a_frag[1] = a0.y; a_frag[2] = a0.z; a_frag[3] = a0.w;
            a_frag[4] = a1.x; a_frag[5] = a1.y; a_frag[6] = a1.z; a_frag[7] = a1.w;
            b_frag[0] = b0.x; b_frag[1] = b0.y; b_frag[2] = b0.z; b_frag[3] = b0.w;
            b_frag[4] = b1.x; b_frag[5] = b1.y; b_frag[6] = b1.z; b_frag[7] = b1.w;
#pragma unroll
            for (int i = 0; i < TM; ++i)
#pragma unroll
                for (int j = 0; j < TN; ++j)
                    acc[i][j] = fmaf(a_frag[i], b_frag[j], acc[i][j]);
        }

        // ---- stage next tile into the other buffer ----
        if (has_next) {
            int ns = s ^ 1;
            As[ns][l_col + 0][l_row] = av.x;
            As[ns][l_col + 1][l_row] = av.y;
            As[ns][l_col + 2][l_row] = av.z;
            As[ns][l_col + 3][l_row] = av.w;
            Bs[ns][l_col + 0][l_row] = bv.x;
            Bs[ns][l_col + 1][l_row] = bv.y;
            Bs[ns][l_col + 2][l_row] = bv.z;
            Bs[ns][l_col + 3][l_row] = bv.w;
        }
        __syncthreads();
        s ^= 1;
    }

    // ---- epilogue: add bias, vectorized store ----
    const int n_base = n0 + tx * TN;
    float4 bias0 = *reinterpret_cast<const float4*>(&bias[n_base]);
    float4 bias1 = *reinterpret_cast<const float4*>(&bias[n_base + 4]);

#pragma unroll
    for (int i = 0; i < TM; ++i) {
        const int m = m0 + ty * TM + i;
        float* crow = C + (size_t)m * N_DIM + n_base;
        float4 v0, v1;
        v0.x = acc[i][0] + bias0.x;
        v0.y = acc[i][1] + bias0.y;
        v0.z = acc[i][2] + bias0.z;
        v0.w = acc[i][3] + bias0.w;
        v1.x = acc[i][4] + bias1.x;
        v1.y = acc[i][5] + bias1.y;
        v1.z = acc[i][6] + bias1.z;
        v1.w = acc[i][7] + bias1.w;
        reinterpret_cast<float4*>(crow)[0] = v0;
        reinterpret_cast<float4*>(crow)[1] = v1;
    }
}

// ---------------------------------------------------------------------------
// Entry point
// ---------------------------------------------------------------------------
extern "C" void kernel_launch(void* const* d_in, const int* in_sizes, int n_in,
                              void* d_out, int out_size) {
    const float* x    = (const float*)d_in[0];   // [4, 2048, 4096]
    const float* w    = (const float*)d_in[1];   // [4096, 4096]
    const float* bias = (const float*)d_in[2];   // [4096]
    const float* sw   = (const float*)d_in[3];   // [262144]
    const int*   idx  = (const int*)d_in[4];     // [2, 262144]
    float* out = (float*)d_out;                  // [8192, 4096]

    // 1) new_weight = W
    {
        const size_t n4 = (size_t)N_DIM * K_DIM / 4;
        int threads = 256;
        int blocks = (int)((n4 + threads - 1) / threads);
        copy_weight_kernel<<<blocks, threads>>>(w);
    }
    // 2) new_weight += scatter(delta)
    {
        int threads = 256;
        int blocks = (NNZ + threads - 1) / threads;
        scatter_delta_kernel<<<blocks, threads>>>(sw, idx);
    }
    // 3) C = x @ new_weight^T + bias
    {
        dim3 grid(N_DIM / BN, M_DIM / BM);   // (32, 64)
        sgemm_kernel<<<grid, 256>>>(x, bias, out);
    }
}

// round 6
// speedup vs baseline: 2.6177x; 2.6177x over previous
#include <cuda_runtime.h>
#include <cuda_bf16.h>
#include <cstdint>
#include <cstddef>

// ---------------------------------------------------------------------------
// Problem constants
// ---------------------------------------------------------------------------
#define K_DIM 4096
#define N_DIM 4096
#define M_DIM 8192
#define NNZ   262144

// GEMM tiling (mma.sync path — compute_103 baseline PTX, no tcgen05)
#define BM 128
#define BN 128
#define BK 64                      // 64 bf16 = 128 B rows (SW128 swizzle)
#define NK (K_DIM / BK)            // 64 chunks
#define STAGES 3

// Stage layout (bytes): Ah | Al | Bh | Bl, each 128 rows x 128 B
#define AH_OFF 0
#define AL_OFF 16384
#define BH_OFF 32768
#define BL_OFF 49152
#define SSIZE  65536
#define DSMEM_BYTES (STAGES * SSIZE + 1024)

// ---------------------------------------------------------------------------
// Device global scratch (allocation-free rule)
// ---------------------------------------------------------------------------
__device__ float         g_newW[(size_t)N_DIM * K_DIM];
__device__ __nv_bfloat16 g_Whi[(size_t)N_DIM * K_DIM];
__device__ __nv_bfloat16 g_Wlo[(size_t)N_DIM * K_DIM];
__device__ __nv_bfloat16 g_Xhi[(size_t)M_DIM * K_DIM];
__device__ __nv_bfloat16 g_Xlo[(size_t)M_DIM * K_DIM];

// ---------------------------------------------------------------------------
// PTX helpers (sm_80-level only: cp.async, ldmatrix, mma.sync)
// ---------------------------------------------------------------------------
__device__ __forceinline__ uint32_t smem_u32(const void* p) {
    uint32_t a;
    asm("{ .reg .u64 t; cvta.to.shared.u64 t, %1; cvt.u32.u64 %0, t; }"
        : "=r"(a) : "l"(p));
    return a;
}

__device__ __forceinline__ void cp16(uint32_t d, const void* s) {
    asm volatile("cp.async.cg.shared.global [%0], [%1], 16;" :: "r"(d), "l"(s) : "memory");
}
__device__ __forceinline__ void cp_commit() { asm volatile("cp.async.commit_group;" ::: "memory"); }
__device__ __forceinline__ void cp_wait1()  { asm volatile("cp.async.wait_group 1;" ::: "memory"); }
__device__ __forceinline__ void cp_wait0()  { asm volatile("cp.async.wait_group 0;" ::: "memory"); }

#define LDSM4(r, addr)                                                          \
    asm volatile("ldmatrix.sync.aligned.m8n8.x4.shared.b16 {%0,%1,%2,%3}, [%4];" \
                 : "=r"((r)[0]), "=r"((r)[1]), "=r"((r)[2]), "=r"((r)[3])        \
                 : "r"(addr))

#define MMA16816(c, a, b0, b1)                                                  \
    asm volatile("mma.sync.aligned.m16n8k16.row.col.f32.bf16.bf16.f32 "         \
                 "{%0,%1,%2,%3},{%4,%5,%6,%7},{%8,%9},{%0,%1,%2,%3};"           \
                 : "+f"((c)[0]), "+f"((c)[1]), "+f"((c)[2]), "+f"((c)[3])       \
                 : "r"((a)[0]), "r"((a)[1]), "r"((a)[2]), "r"((a)[3]),          \
                   "r"(b0), "r"(b1))

// ---------------------------------------------------------------------------
// Kernel 1: copy W -> g_newW
// ---------------------------------------------------------------------------
__global__ void copy_weight_kernel(const float* __restrict__ w) {
    size_t i = (size_t)blockIdx.x * blockDim.x + threadIdx.x;
    const size_t n4 = (size_t)N_DIM * K_DIM / 4;
    if (i < n4)
        reinterpret_cast<float4*>(g_newW)[i] = reinterpret_cast<const float4*>(w)[i];
}

// ---------------------------------------------------------------------------
// Kernel 2: scatter shira delta (atomics; duplicates accumulate)
// ---------------------------------------------------------------------------
__global__ void scatter_delta_kernel(const float* __restrict__ sw, const int* __restrict__ idx) {
    int i = blockIdx.x * blockDim.x + threadIdx.x;
    if (i < NNZ) {
        int r = idx[i];
        int c = idx[NNZ + i];
        atomicAdd(&g_newW[(size_t)r * K_DIM + c], sw[i]);
    }
}

// ---------------------------------------------------------------------------
// bf16 hi/lo split + conversion kernels
// ---------------------------------------------------------------------------
__device__ __forceinline__ void split_store4(float4 v,
                                             __nv_bfloat16* __restrict__ hi,
                                             __nv_bfloat16* __restrict__ lo,
                                             size_t elem_base) {
    float f[4] = {v.x, v.y, v.z, v.w};
    __nv_bfloat16 h[4], l[4];
#pragma unroll
    for (int j = 0; j < 4; ++j) {
        h[j] = __float2bfloat16(f[j]);
        l[j] = __float2bfloat16(f[j] - __bfloat162float(h[j]));
    }
    __nv_bfloat162 h01, h23, l01, l23;
    h01.x = h[0]; h01.y = h[1]; h23.x = h[2]; h23.y = h[3];
    l01.x = l[0]; l01.y = l[1]; l23.x = l[2]; l23.y = l[3];
    uint2 hv, lv;
    hv.x = *reinterpret_cast<uint32_t*>(&h01);
    hv.y = *reinterpret_cast<uint32_t*>(&h23);
    lv.x = *reinterpret_cast<uint32_t*>(&l01);
    lv.y = *reinterpret_cast<uint32_t*>(&l23);
    *reinterpret_cast<uint2*>(hi + elem_base) = hv;
    *reinterpret_cast<uint2*>(lo + elem_base) = lv;
}

__global__ void convert_w_kernel() {
    size_t i = (size_t)blockIdx.x * blockDim.x + threadIdx.x;
    const size_t n4 = (size_t)N_DIM * K_DIM / 4;
    if (i < n4) {
        float4 v = reinterpret_cast<const float4*>(g_newW)[i];
        split_store4(v, g_Whi, g_Wlo, i * 4);
    }
}

__global__ void convert_x_kernel(const float* __restrict__ x) {
    size_t i = (size_t)blockIdx.x * blockDim.x + threadIdx.x;
    const size_t n4 = (size_t)M_DIM * K_DIM / 4;
    if (i < n4) {
        float4 v = reinterpret_cast<const float4*>(x)[i];
        split_store4(v, g_Xhi, g_Xlo, i * 4);
    }
}

// ---------------------------------------------------------------------------
// Kernel 3: bf16x3 GEMM via mma.sync.m16n8k16
//   out[M,N] = Xhi*Whi^T + Xhi*Wlo^T + Xlo*Whi^T + bias
// CTA 128x128, BK=64, 3-stage cp.async, 8 warps (warp tile 64x32).
// ---------------------------------------------------------------------------
extern __shared__ char dsm[];

__device__ __forceinline__ void load_stage(uint32_t st, int chunk, int tid,
                                           const char* pAh, const char* pAl,
                                           const char* pBh, const char* pBl) {
    const size_t koff = (size_t)chunk * 128;   // bytes into each row
#pragma unroll
    for (int j = 0; j < 4; ++j) {              // 128 rows x 8 segs = 1024 / 256 thr
        int o  = j * 256 + tid;
        int r  = o >> 3;
        int sg = o & 7;
        size_t go = (size_t)r * (K_DIM * 2) + koff + (size_t)sg * 16;
        uint32_t so = (uint32_t)(r * 128) + (uint32_t)((sg * 16) ^ ((r & 7) << 4));
        cp16(st + AH_OFF + so, pAh + go);
        cp16(st + AL_OFF + so, pAl + go);
        cp16(st + BH_OFF + so, pBh + go);
        cp16(st + BL_OFF + so, pBl + go);
    }
}

__global__ void __launch_bounds__(256, 1)
gemm_bf16x3_mma_kernel(const float* __restrict__ bias, float* __restrict__ out) {
    const int tid  = threadIdx.x;
    const int wid  = tid >> 5;
    const int lane = tid & 31;
    const int wm   = wid & 1;       // 2 M-slots of 64 rows
    const int wn   = wid >> 1;      // 4 N-slots of 32 cols

    const int m0 = blockIdx.y * BM;
    const int n0 = blockIdx.x * BN;

    uint32_t sb = (smem_u32(dsm) + 1023u) & ~1023u;

    const char* pAh = (const char*)g_Xhi + (size_t)m0 * (K_DIM * 2);
    const char* pAl = (const char*)g_Xlo + (size_t)m0 * (K_DIM * 2);
    const char* pBh = (const char*)g_Whi + (size_t)n0 * (K_DIM * 2);
    const char* pBl = (const char*)g_Wlo + (size_t)n0 * (K_DIM * 2);

    float acc[4][4][4];
#pragma unroll
    for (int i = 0; i < 4; ++i)
#pragma unroll
        for (int j = 0; j < 4; ++j)
#pragma unroll
            for (int q = 0; q < 4; ++q) acc[i][j][q] = 0.0f;

    // Per-lane ldmatrix addressing.
    // Tile row = base(mult of 8) + (lane&15)  -> row&7 == lane&7, so the SW128
    // XOR term ((row&7)<<4) is a per-lane constant folded into xks[].
    const int l15 = lane & 15;
    const int lhi = lane >> 4;
    const uint32_t lsw = (uint32_t)((lane & 7) << 4);
    uint32_t xks[4];
#pragma unroll
    for (int ks = 0; ks < 4; ++ks)
        xks[ks] = (uint32_t)(ks * 32 + lhi * 16) ^ lsw;

    const uint32_t aRow = (uint32_t)((wm * 64 + l15) * 128);
    const uint32_t bRow = (uint32_t)((wn * 32 + l15) * 128);

    // Prologue: stages 0 and 1 in flight
    load_stage(sb, 0, tid, pAh, pAl, pBh, pBl);
    cp_commit();
    load_stage(sb + SSIZE, 1, tid, pAh, pAl, pBh, pBl);
    cp_commit();

    for (int kt = 0; kt < NK; ++kt) {
        if (kt + 1 < NK) cp_wait1(); else cp_wait0();
        __syncthreads();

        if (kt + 2 < NK) {
            load_stage(sb + ((kt + 2) % STAGES) * SSIZE, kt + 2, tid,
                       pAh, pAl, pBh, pBl);
            cp_commit();
        }

        const uint32_t slot = sb + (kt % STAGES) * SSIZE;
#pragma unroll
        for (int ks = 0; ks < 4; ++ks) {
            uint32_t ah[16], al[16], bh[8], bl[8];
#pragma unroll
            for (int mi = 0; mi < 4; ++mi) {
                uint32_t ra = slot + aRow + (uint32_t)(mi * 2048) + xks[ks];
                LDSM4(ah + mi * 4, ra + AH_OFF);
                LDSM4(al + mi * 4, ra + AL_OFF);
            }
#pragma unroll
            for (int nb = 0; nb < 2; ++nb) {
                uint32_t rb = slot + bRow + (uint32_t)(nb * 2048) + xks[ks];
                LDSM4(bh + nb * 4, rb + BH_OFF);
                LDSM4(bl + nb * 4, rb + BL_OFF);
            }
#pragma unroll
            for (int mi = 0; mi < 4; ++mi) {
#pragma unroll
                for (int j = 0; j < 4; ++j) {
                    const int nb = j >> 1, s = j & 1;
                    MMA16816(acc[mi][j], ah + mi * 4, bh[nb * 4 + s], bh[nb * 4 + 2 + s]);
                    MMA16816(acc[mi][j], ah + mi * 4, bl[nb * 4 + s], bl[nb * 4 + 2 + s]);
                    MMA16816(acc[mi][j], al + mi * 4, bh[nb * 4 + s], bh[nb * 4 + 2 + s]);
                }
            }
        }
    }

    // Epilogue: C frag (m16n8): c0,c1 at (m = l>>2, n = 2*(l&3)); c2,c3 at m+8.
    const int mBase = m0 + wm * 64;
    const int nBase = n0 + wn * 32;
    const int rsub  = lane >> 2;
    const int csub  = (lane & 3) * 2;
#pragma unroll
    for (int j = 0; j < 4; ++j) {
        const int n = nBase + j * 8 + csub;
        const float2 b2 = *reinterpret_cast<const float2*>(bias + n);
#pragma unroll
        for (int mi = 0; mi < 4; ++mi) {
            const int r0 = mBase + mi * 16 + rsub;
            float2 v0, v1;
            v0.x = acc[mi][j][0] + b2.x;
            v0.y = acc[mi][j][1] + b2.y;
            v1.x = acc[mi][j][2] + b2.x;
            v1.y = acc[mi][j][3] + b2.y;
            *reinterpret_cast<float2*>(out + (size_t)r0 * N_DIM + n)       = v0;
            *reinterpret_cast<float2*>(out + (size_t)(r0 + 8) * N_DIM + n) = v1;
        }
    }
}

// ---------------------------------------------------------------------------
// Entry point
// ---------------------------------------------------------------------------
extern "C" void kernel_launch(void* const* d_in, const int* in_sizes, int n_in,
                              void* d_out, int out_size) {
    const float* x    = (const float*)d_in[0];   // [4, 2048, 4096]
    const float* w    = (const float*)d_in[1];   // [4096, 4096]
    const float* bias = (const float*)d_in[2];   // [4096]
    const float* sw   = (const float*)d_in[3];   // [262144]
    const int*   idx  = (const int*)d_in[4];     // [2, 262144]
    float* out = (float*)d_out;                  // [8192, 4096]

    {
        const size_t n4 = (size_t)N_DIM * K_DIM / 4;
        copy_weight_kernel<<<(int)((n4 + 255) / 256), 256>>>(w);
    }
    scatter_delta_kernel<<<(NNZ + 255) / 256, 256>>>(sw, idx);
    {
        const size_t n4 = (size_t)N_DIM * K_DIM / 4;
        convert_w_kernel<<<(int)((n4 + 255) / 256), 256>>>();
    }
    {
        const size_t n4 = (size_t)M_DIM * K_DIM / 4;
        convert_x_kernel<<<(int)((n4 + 255) / 256), 256>>>(x);
    }
    {
        cudaFuncSetAttribute(gemm_bf16x3_mma_kernel,
                             cudaFuncAttributeMaxDynamicSharedMemorySize, DSMEM_BYTES);
        dim3 grid(N_DIM / BN, M_DIM / BM);   // (32, 64)
        gemm_bf16x3_mma_kernel<<<grid, 256, DSMEM_BYTES>>>(bias, out);
    }
}

// round 8
// speedup vs baseline: 4.9976x; 1.9091x over previous
#include <cuda_runtime.h>
#include <cuda_fp16.h>
#include <cstdint>
#include <cstddef>

// ---------------------------------------------------------------------------
// Problem constants
// ---------------------------------------------------------------------------
#define K_DIM 4096
#define N_DIM 4096
#define M_DIM 8192
#define NNZ   262144

// GEMM tiling — single-pass fp16 mma.sync
#define BM 128
#define BN 128
#define BK 64                      // 64 fp16 = 128 B rows (SW128-style XOR swizzle)
#define NK (K_DIM / BK)            // 64 chunks
#define STAGES 3

// Stage layout (bytes): A | B, each 128 rows x 128 B
#define A_OFF 0
#define B_OFF 16384
#define SSIZE 32768
#define DSMEM_BYTES (STAGES * SSIZE + 1024)   // ~97 KB -> 2 CTAs/SM

// ---------------------------------------------------------------------------
// Device global scratch (allocation-free rule)
// ---------------------------------------------------------------------------
__device__ float  g_newW[(size_t)N_DIM * K_DIM];
__device__ __half g_Wh[(size_t)N_DIM * K_DIM];
__device__ __half g_Xh[(size_t)M_DIM * K_DIM];

// ---------------------------------------------------------------------------
// PTX helpers (sm_80-level only: cp.async, ldmatrix, mma.sync)
// ---------------------------------------------------------------------------
__device__ __forceinline__ uint32_t smem_u32(const void* p) {
    uint32_t a;
    asm("{ .reg .u64 t; cvta.to.shared.u64 t, %1; cvt.u32.u64 %0, t; }"
        : "=r"(a) : "l"(p));
    return a;
}

__device__ __forceinline__ void cp16(uint32_t d, const void* s) {
    asm volatile("cp.async.cg.shared.global [%0], [%1], 16;" :: "r"(d), "l"(s) : "memory");
}
__device__ __forceinline__ void cp_commit() { asm volatile("cp.async.commit_group;" ::: "memory"); }
__device__ __forceinline__ void cp_wait1()  { asm volatile("cp.async.wait_group 1;" ::: "memory"); }
__device__ __forceinline__ void cp_wait0()  { asm volatile("cp.async.wait_group 0;" ::: "memory"); }

#define LDSM4(r, addr)                                                          \
    asm volatile("ldmatrix.sync.aligned.m8n8.x4.shared.b16 {%0,%1,%2,%3}, [%4];" \
                 : "=r"((r)[0]), "=r"((r)[1]), "=r"((r)[2]), "=r"((r)[3])        \
                 : "r"(addr))

#define MMA16816(c, a, b0, b1)                                                  \
    asm volatile("mma.sync.aligned.m16n8k16.row.col.f32.f16.f16.f32 "           \
                 "{%0,%1,%2,%3},{%4,%5,%6,%7},{%8,%9},{%0,%1,%2,%3};"           \
                 : "+f"((c)[0]), "+f"((c)[1]), "+f"((c)[2]), "+f"((c)[3])       \
                 : "r"((a)[0]), "r"((a)[1]), "r"((a)[2]), "r"((a)[3]),          \
                   "r"(b0), "r"(b1))

// ---------------------------------------------------------------------------
// Kernel 1: copy W -> g_newW
// ---------------------------------------------------------------------------
__global__ void copy_weight_kernel(const float* __restrict__ w) {
    size_t i = (size_t)blockIdx.x * blockDim.x + threadIdx.x;
    const size_t n4 = (size_t)N_DIM * K_DIM / 4;
    if (i < n4)
        reinterpret_cast<float4*>(g_newW)[i] = reinterpret_cast<const float4*>(w)[i];
}

// ---------------------------------------------------------------------------
// Kernel 2: scatter shira delta (atomics; duplicates accumulate)
// ---------------------------------------------------------------------------
__global__ void scatter_delta_kernel(const float* __restrict__ sw, const int* __restrict__ idx) {
    int i = blockIdx.x * blockDim.x + threadIdx.x;
    if (i < NNZ) {
        int r = idx[i];
        int c = idx[NNZ + i];
        atomicAdd(&g_newW[(size_t)r * K_DIM + c], sw[i]);
    }
}

// ---------------------------------------------------------------------------
// fp16 conversion kernels
// ---------------------------------------------------------------------------
__device__ __forceinline__ void h4_store(float4 v, __half* __restrict__ dst, size_t base) {
    __half2 p01 = __floats2half2_rn(v.x, v.y);
    __half2 p23 = __floats2half2_rn(v.z, v.w);
    uint2 u;
    u.x = *reinterpret_cast<uint32_t*>(&p01);
    u.y = *reinterpret_cast<uint32_t*>(&p23);
    *reinterpret_cast<uint2*>(dst + base) = u;
}

__global__ void convert_w_kernel() {
    size_t i = (size_t)blockIdx.x * blockDim.x + threadIdx.x;
    const size_t n4 = (size_t)N_DIM * K_DIM / 4;
    if (i < n4) {
        float4 v = reinterpret_cast<const float4*>(g_newW)[i];
        h4_store(v, g_Wh, i * 4);
    }
}

__global__ void convert_x_kernel(const float* __restrict__ x) {
    size_t i = (size_t)blockIdx.x * blockDim.x + threadIdx.x;
    const size_t n4 = (size_t)M_DIM * K_DIM / 4;
    if (i < n4) {
        float4 v = reinterpret_cast<const float4*>(x)[i];
        h4_store(v, g_Xh, i * 4);
    }
}

// ---------------------------------------------------------------------------
// Kernel 3: fp16 single-pass GEMM via mma.sync.m16n8k16
//   out[M,N] = fp16(X) * fp16(W')^T + bias   (fp32 accumulate)
// CTA 128x128, BK=64, 3-stage cp.async, 8 warps (warp tile 64x32), 2 CTAs/SM.
// ---------------------------------------------------------------------------
extern __shared__ char dsm[];

__device__ __forceinline__ void load_stage(uint32_t st, int chunk, int tid,
                                           const char* pA, const char* pB) {
    const size_t koff = (size_t)chunk * 128;   // bytes into each row
#pragma unroll
    for (int j = 0; j < 4; ++j) {              // 128 rows x 8 segs = 1024 / 256 thr
        int o  = j * 256 + tid;
        int r  = o >> 3;
        int sg = o & 7;
        size_t go = (size_t)r * (K_DIM * 2) + koff + (size_t)sg * 16;
        uint32_t so = (uint32_t)(r * 128) + (uint32_t)((sg * 16) ^ ((r & 7) << 4));
        cp16(st + A_OFF + so, pA + go);
        cp16(st + B_OFF + so, pB + go);
    }
}

__global__ void __launch_bounds__(256, 2)
gemm_fp16_mma_kernel(const float* __restrict__ bias, float* __restrict__ out) {
    const int tid  = threadIdx.x;
    const int wid  = tid >> 5;
    const int lane = tid & 31;
    const int wm   = wid & 1;       // 2 M-slots of 64 rows
    const int wn   = wid >> 1;      // 4 N-slots of 32 cols

    const int m0 = blockIdx.y * BM;
    const int n0 = blockIdx.x * BN;

    uint32_t sb = (smem_u32(dsm) + 1023u) & ~1023u;

    const char* pA = (const char*)g_Xh + (size_t)m0 * (K_DIM * 2);
    const char* pB = (const char*)g_Wh + (size_t)n0 * (K_DIM * 2);

    float acc[4][4][4];
#pragma unroll
    for (int i = 0; i < 4; ++i)
#pragma unroll
        for (int j = 0; j < 4; ++j)
#pragma unroll
            for (int q = 0; q < 4; ++q) acc[i][j][q] = 0.0f;

    // Per-lane ldmatrix addressing (tile row = base + (lane&15); row&7 == lane&7,
    // so the XOR swizzle term is a per-lane constant folded into xks[]).
    const int l15 = lane & 15;
    const int lhi = lane >> 4;
    const uint32_t lsw = (uint32_t)((lane & 7) << 4);
    uint32_t xks[4];
#pragma unroll
    for (int ks = 0; ks < 4; ++ks)
        xks[ks] = (uint32_t)(ks * 32 + lhi * 16) ^ lsw;

    const uint32_t aRow = (uint32_t)((wm * 64 + l15) * 128);
    const uint32_t bRow = (uint32_t)((wn * 32 + l15) * 128);

    // Prologue: stages 0 and 1 in flight
    load_stage(sb, 0, tid, pA, pB);
    cp_commit();
    load_stage(sb + SSIZE, 1, tid, pA, pB);
    cp_commit();

    for (int kt = 0; kt < NK; ++kt) {
        if (kt + 1 < NK) cp_wait1(); else cp_wait0();
        __syncthreads();

        if (kt + 2 < NK) {
            load_stage(sb + ((kt + 2) % STAGES) * SSIZE, kt + 2, tid, pA, pB);
            cp_commit();
        }

        const uint32_t slot = sb + (kt % STAGES) * SSIZE;
#pragma unroll
        for (int ks = 0; ks < 4; ++ks) {
            uint32_t a[16], b[8];
#pragma unroll
            for (int mi = 0; mi < 4; ++mi) {
                uint32_t ra = slot + A_OFF + aRow + (uint32_t)(mi * 2048) + xks[ks];
                LDSM4(a + mi * 4, ra);
            }
#pragma unroll
            for (int nb = 0; nb < 2; ++nb) {
                uint32_t rb = slot + B_OFF + bRow + (uint32_t)(nb * 2048) + xks[ks];
                LDSM4(b + nb * 4, rb);
            }
#pragma unroll
            for (int mi = 0; mi < 4; ++mi) {
#pragma unroll
                for (int j = 0; j < 4; ++j) {
                    const int nb = j >> 1, s = j & 1;
                    MMA16816(acc[mi][j], a + mi * 4, b[nb * 4 + s], b[nb * 4 + 2 + s]);
                }
            }
        }
    }

    // Epilogue: C frag (m16n8): c0,c1 at (m = l>>2, n = 2*(l&3)); c2,c3 at m+8.
    const int mBase = m0 + wm * 64;
    const int nBase = n0 + wn * 32;
    const int rsub  = lane >> 2;
    const int csub  = (lane & 3) * 2;
#pragma unroll
    for (int j = 0; j < 4; ++j) {
        const int n = nBase + j * 8 + csub;
        const float2 b2 = *reinterpret_cast<const float2*>(bias + n);
#pragma unroll
        for (int mi = 0; mi < 4; ++mi) {
            const int r0 = mBase + mi * 16 + rsub;
            float2 v0, v1;
            v0.x = acc[mi][j][0] + b2.x;
            v0.y = acc[mi][j][1] + b2.y;
            v1.x = acc[mi][j][2] + b2.x;
            v1.y = acc[mi][j][3] + b2.y;
            *reinterpret_cast<float2*>(out + (size_t)r0 * N_DIM + n)       = v0;
            *reinterpret_cast<float2*>(out + (size_t)(r0 + 8) * N_DIM + n) = v1;
        }
    }
}

// ---------------------------------------------------------------------------
// Entry point
// ---------------------------------------------------------------------------
extern "C" void kernel_launch(void* const* d_in, const int* in_sizes, int n_in,
                              void* d_out, int out_size) {
    const float* x    = (const float*)d_in[0];   // [4, 2048, 4096]
    const float* w    = (const float*)d_in[1];   // [4096, 4096]
    const float* bias = (const float*)d_in[2];   // [4096]
    const float* sw   = (const float*)d_in[3];   // [262144]
    const int*   idx  = (const int*)d_in[4];     // [2, 262144]
    float* out = (float*)d_out;                  // [8192, 4096]

    {
        const size_t n4 = (size_t)N_DIM * K_DIM / 4;
        copy_weight_kernel<<<(int)((n4 + 255) / 256), 256>>>(w);
    }
    scatter_delta_kernel<<<(NNZ + 255) / 256, 256>>>(sw, idx);
    {
        const size_t n4 = (size_t)N_DIM * K_DIM / 4;
        convert_w_kernel<<<(int)((n4 + 255) / 256), 256>>>();
    }
    {
        const size_t n4 = (size_t)M_DIM * K_DIM / 4;
        convert_x_kernel<<<(int)((n4 + 255) / 256), 256>>>(x);
    }
    {
        cudaFuncSetAttribute(gemm_fp16_mma_kernel,
                             cudaFuncAttributeMaxDynamicSharedMemorySize, DSMEM_BYTES);
        dim3 grid(N_DIM / BN, M_DIM / BM);   // (32, 64)
        gemm_fp16_mma_kernel<<<grid, 256, DSMEM_BYTES>>>(bias, out);
    }
}

// round 9
// speedup vs baseline: 7.3300x; 1.4667x over previous
#include <cuda_runtime.h>
#include <cuda_fp16.h>
#include <cstdint>
#include <cstddef>

// ---------------------------------------------------------------------------
// Problem constants
// ---------------------------------------------------------------------------
#define K_DIM 4096
#define N_DIM 4096
#define M_DIM 8192
#define NNZ   262144

// GEMM tiling — single-pass fp16 mma.sync, CTA 128x256, warp tile 64x64
#define BM 128
#define BN 256
#define BK 64                      // 64 fp16 = 128 B rows (XOR-swizzled)
#define NK (K_DIM / BK)            // 64 chunks
#define STAGES 4

// Stage layout (bytes): A (128 rows x 128B) | B (256 rows x 128B)
#define A_OFF 0
#define B_OFF 16384
#define SSIZE 49152
#define DSMEM_BYTES (STAGES * SSIZE + 1024)   // ~193 KB -> 1 CTA/SM

// ---------------------------------------------------------------------------
// Device global scratch (allocation-free rule)
// ---------------------------------------------------------------------------
__device__ float  g_newW[(size_t)N_DIM * K_DIM];
__device__ __half g_Wh[(size_t)N_DIM * K_DIM];
__device__ __half g_Xh[(size_t)M_DIM * K_DIM];

// ---------------------------------------------------------------------------
// PTX helpers (sm_80-level only: cp.async, ldmatrix, mma.sync)
// ---------------------------------------------------------------------------
__device__ __forceinline__ uint32_t smem_u32(const void* p) {
    uint32_t a;
    asm("{ .reg .u64 t; cvta.to.shared.u64 t, %1; cvt.u32.u64 %0, t; }"
        : "=r"(a) : "l"(p));
    return a;
}

__device__ __forceinline__ void cp16(uint32_t d, const void* s) {
    asm volatile("cp.async.cg.shared.global [%0], [%1], 16;" :: "r"(d), "l"(s) : "memory");
}
__device__ __forceinline__ void cp_commit() { asm volatile("cp.async.commit_group;" ::: "memory"); }
__device__ __forceinline__ void cp_wait2()  { asm volatile("cp.async.wait_group 2;" ::: "memory"); }
__device__ __forceinline__ void cp_wait1()  { asm volatile("cp.async.wait_group 1;" ::: "memory"); }
__device__ __forceinline__ void cp_wait0()  { asm volatile("cp.async.wait_group 0;" ::: "memory"); }

#define LDSM4(r, addr)                                                          \
    asm volatile("ldmatrix.sync.aligned.m8n8.x4.shared.b16 {%0,%1,%2,%3}, [%4];" \
                 : "=r"((r)[0]), "=r"((r)[1]), "=r"((r)[2]), "=r"((r)[3])        \
                 : "r"(addr))

#define MMA16816(c, a, b0, b1)                                                  \
    asm volatile("mma.sync.aligned.m16n8k16.row.col.f32.f16.f16.f32 "           \
                 "{%0,%1,%2,%3},{%4,%5,%6,%7},{%8,%9},{%0,%1,%2,%3};"           \
                 : "+f"((c)[0]), "+f"((c)[1]), "+f"((c)[2]), "+f"((c)[3])       \
                 : "r"((a)[0]), "r"((a)[1]), "r"((a)[2]), "r"((a)[3]),          \
                   "r"(b0), "r"(b1))

// ---------------------------------------------------------------------------
// Kernel 1: copy W -> g_newW
// ---------------------------------------------------------------------------
__global__ void copy_weight_kernel(const float* __restrict__ w) {
    size_t i = (size_t)blockIdx.x * blockDim.x + threadIdx.x;
    const size_t n4 = (size_t)N_DIM * K_DIM / 4;
    if (i < n4)
        reinterpret_cast<float4*>(g_newW)[i] = reinterpret_cast<const float4*>(w)[i];
}

// ---------------------------------------------------------------------------
// Kernel 2: scatter shira delta (atomics; duplicates accumulate)
// ---------------------------------------------------------------------------
__global__ void scatter_delta_kernel(const float* __restrict__ sw, const int* __restrict__ idx) {
    int i = blockIdx.x * blockDim.x + threadIdx.x;
    if (i < NNZ) {
        int r = idx[i];
        int c = idx[NNZ + i];
        atomicAdd(&g_newW[(size_t)r * K_DIM + c], sw[i]);
    }
}

// ---------------------------------------------------------------------------
// fp16 conversion kernels
// ---------------------------------------------------------------------------
__device__ __forceinline__ void h4_store(float4 v, __half* __restrict__ dst, size_t base) {
    __half2 p01 = __floats2half2_rn(v.x, v.y);
    __half2 p23 = __floats2half2_rn(v.z, v.w);
    uint2 u;
    u.x = *reinterpret_cast<uint32_t*>(&p01);
    u.y = *reinterpret_cast<uint32_t*>(&p23);
    *reinterpret_cast<uint2*>(dst + base) = u;
}

__global__ void convert_w_kernel() {
    size_t i = (size_t)blockIdx.x * blockDim.x + threadIdx.x;
    const size_t n4 = (size_t)N_DIM * K_DIM / 4;
    if (i < n4) {
        float4 v = reinterpret_cast<const float4*>(g_newW)[i];
        h4_store(v, g_Wh, i * 4);
    }
}

__global__ void convert_x_kernel(const float* __restrict__ x) {
    size_t i = (size_t)blockIdx.x * blockDim.x + threadIdx.x;
    const size_t n4 = (size_t)M_DIM * K_DIM / 4;
    if (i < n4) {
        float4 v = reinterpret_cast<const float4*>(x)[i];
        h4_store(v, g_Xh, i * 4);
    }
}

// ---------------------------------------------------------------------------
// Kernel 3: fp16 GEMM via mma.sync.m16n8k16
//   out[M,N] = fp16(X) * fp16(W')^T + bias  (fp32 accumulate)
// CTA 128x256, 8 warps (2x4), warp tile 64x64, BK=64, 4-stage cp.async.
// ---------------------------------------------------------------------------
extern __shared__ char dsm[];

__device__ __forceinline__ void load_stage(uint32_t st, int chunk, int tid,
                                           const char* pA, const char* pB) {
    const size_t koff = (size_t)chunk * 128;   // bytes into each K-major row
#pragma unroll
    for (int j = 0; j < 4; ++j) {              // A: 128 rows x 8 segs = 1024 ops
        int o  = j * 256 + tid;
        int r  = o >> 3;
        int sg = o & 7;
        size_t go = (size_t)r * (K_DIM * 2) + koff + (size_t)sg * 16;
        uint32_t so = (uint32_t)(r * 128) + (uint32_t)((sg * 16) ^ ((r & 7) << 4));
        cp16(st + A_OFF + so, pA + go);
    }
#pragma unroll
    for (int j = 0; j < 8; ++j) {              // B: 256 rows x 8 segs = 2048 ops
        int o  = j * 256 + tid;
        int r  = o >> 3;
        int sg = o & 7;
        size_t go = (size_t)r * (K_DIM * 2) + koff + (size_t)sg * 16;
        uint32_t so = (uint32_t)(r * 128) + (uint32_t)((sg * 16) ^ ((r & 7) << 4));
        cp16(st + B_OFF + so, pB + go);
    }
}

__global__ void __launch_bounds__(256, 1)
gemm_fp16_mma_kernel(const float* __restrict__ bias, float* __restrict__ out) {
    const int tid  = threadIdx.x;
    const int wid  = tid >> 5;
    const int lane = tid & 31;
    const int wm   = wid & 1;       // 2 M-slots of 64 rows
    const int wn   = wid >> 1;      // 4 N-slots of 64 cols

    const int m0 = blockIdx.y * BM;
    const int n0 = blockIdx.x * BN;

    uint32_t sb = (smem_u32(dsm) + 1023u) & ~1023u;

    const char* pA = (const char*)g_Xh + (size_t)m0 * (K_DIM * 2);
    const char* pB = (const char*)g_Wh + (size_t)n0 * (K_DIM * 2);

    float acc[4][8][4];
#pragma unroll
    for (int i = 0; i < 4; ++i)
#pragma unroll
        for (int j = 0; j < 8; ++j)
#pragma unroll
            for (int q = 0; q < 4; ++q) acc[i][j][q] = 0.0f;

    // Per-lane ldmatrix addressing (tile row = base + (lane&15); row&7 == lane&7,
    // so the XOR swizzle term is a per-lane constant folded into xks[]).
    const int l15 = lane & 15;
    const int lhi = lane >> 4;
    const uint32_t lsw = (uint32_t)((lane & 7) << 4);
    uint32_t xks[4];
#pragma unroll
    for (int ks = 0; ks < 4; ++ks)
        xks[ks] = (uint32_t)(ks * 32 + lhi * 16) ^ lsw;

    const uint32_t aRow = (uint32_t)((wm * 64 + l15) * 128);
    const uint32_t bRow = (uint32_t)((wn * 64 + l15) * 128);

    // Prologue: stages 0..2 in flight
    load_stage(sb, 0, tid, pA, pB);
    cp_commit();
    load_stage(sb + SSIZE, 1, tid, pA, pB);
    cp_commit();
    load_stage(sb + 2 * SSIZE, 2, tid, pA, pB);
    cp_commit();

    for (int kt = 0; kt < NK; ++kt) {
        const int remaining = NK - 1 - kt;     // groups after this one
        if (remaining >= 2)      cp_wait2();
        else if (remaining == 1) cp_wait1();
        else                     cp_wait0();
        __syncthreads();

        if (kt + 3 < NK) {
            load_stage(sb + ((kt + 3) & 3) * SSIZE, kt + 3, tid, pA, pB);
            cp_commit();
        }

        const uint32_t slot = sb + (kt & 3) * SSIZE;
#pragma unroll
        for (int ks = 0; ks < 4; ++ks) {
            uint32_t a[16], b[16];
#pragma unroll
            for (int mi = 0; mi < 4; ++mi)
                LDSM4(a + mi * 4, slot + A_OFF + aRow + (uint32_t)(mi * 2048) + xks[ks]);
#pragma unroll
            for (int nb = 0; nb < 4; ++nb)
                LDSM4(b + nb * 4, slot + B_OFF + bRow + (uint32_t)(nb * 2048) + xks[ks]);
#pragma unroll
            for (int mi = 0; mi < 4; ++mi) {
#pragma unroll
                for (int j = 0; j < 8; ++j) {
                    const int g = j >> 1, s = j & 1;
                    MMA16816(acc[mi][j], a + mi * 4, b[g * 4 + s], b[g * 4 + 2 + s]);
                }
            }
        }
    }

    // Epilogue: C frag (m16n8): c0,c1 at (m = l>>2, n = 2*(l&3)); c2,c3 at m+8.
    const int mBase = m0 + wm * 64;
    const int nBase = n0 + wn * 64;
    const int rsub  = lane >> 2;
    const int csub  = (lane & 3) * 2;
#pragma unroll
    for (int j = 0; j < 8; ++j) {
        const int n = nBase + j * 8 + csub;
        const float2 b2 = *reinterpret_cast<const float2*>(bias + n);
#pragma unroll
        for (int mi = 0; mi < 4; ++mi) {
            const int r0 = mBase + mi * 16 + rsub;
            float2 v0, v1;
            v0.x = acc[mi][j][0] + b2.x;
            v0.y = acc[mi][j][1] + b2.y;
            v1.x = acc[mi][j][2] + b2.x;
            v1.y = acc[mi][j][3] + b2.y;
            *reinterpret_cast<float2*>(out + (size_t)r0 * N_DIM + n)       = v0;
            *reinterpret_cast<float2*>(out + (size_t)(r0 + 8) * N_DIM + n) = v1;
        }
    }
}

// ---------------------------------------------------------------------------
// Entry point
// ---------------------------------------------------------------------------
extern "C" void kernel_launch(void* const* d_in, const int* in_sizes, int n_in,
                              void* d_out, int out_size) {
    const float* x    = (const float*)d_in[0];   // [4, 2048, 4096]
    const float* w    = (const float*)d_in[1];   // [4096, 4096]
    const float* bias = (const float*)d_in[2];   // [4096]
    const float* sw   = (const float*)d_in[3];   // [262144]
    const int*   idx  = (const int*)d_in[4];     // [2, 262144]
    float* out = (float*)d_out;                  // [8192, 4096]

    {
        const size_t n4 = (size_t)N_DIM * K_DIM / 4;
        copy_weight_kernel<<<(int)((n4 + 255) / 256), 256>>>(w);
    }
    scatter_delta_kernel<<<(NNZ + 255) / 256, 256>>>(sw, idx);
    {
        const size_t n4 = (size_t)N_DIM * K_DIM / 4;
        convert_w_kernel<<<(int)((n4 + 255) / 256), 256>>>();
    }
    {
        const size_t n4 = (size_t)M_DIM * K_DIM / 4;
        convert_x_kernel<<<(int)((n4 + 255) / 256), 256>>>(x);
    }
    {
        cudaFuncSetAttribute(gemm_fp16_mma_kernel,
                             cudaFuncAttributeMaxDynamicSharedMemorySize, DSMEM_BYTES);
        dim3 grid(N_DIM / BN, M_DIM / BM);   // (16, 64)
        gemm_fp16_mma_kernel<<<grid, 256, DSMEM_BYTES>>>(bias, out);
    }
}

// round 12
// speedup vs baseline: 7.5029x; 1.0236x over previous
#include <cuda_runtime.h>
#include <cuda_fp16.h>
#include <cstdint>
#include <cstddef>

// ---------------------------------------------------------------------------
// Problem constants
// ---------------------------------------------------------------------------
#define K_DIM 4096
#define N_DIM 4096
#define M_DIM 8192
#define NNZ   262144

// GEMM tiling — fp16 mma.sync, CTA 128x256, warp tile 64x64
#define BM 128
#define BN 256
#define BK 64                      // 64 fp16 = 128 B rows (XOR-swizzled)
#define NK (K_DIM / BK)            // 64 chunks
#define STAGES 4

// Stage layout (bytes): A (128 rows x 128B) | B (256 rows x 128B)
#define A_OFF 0
#define B_OFF 16384
#define SSIZE 49152
#define DSMEM_BYTES (STAGES * SSIZE + 1024)   // ~193 KB -> 1 CTA/SM

// ---------------------------------------------------------------------------
// Device global scratch (allocation-free rule)
// ---------------------------------------------------------------------------
__device__ __half g_Wh[(size_t)N_DIM * K_DIM];
__device__ __half g_Xh[(size_t)M_DIM * K_DIM];

// ---------------------------------------------------------------------------
// PTX helpers (sm_80-level only: cp.async, ldmatrix, mma.sync)
// ---------------------------------------------------------------------------
__device__ __forceinline__ uint32_t smem_u32(const void* p) {
    uint32_t a;
    asm("{ .reg .u64 t; cvta.to.shared.u64 t, %1; cvt.u32.u64 %0, t; }"
        : "=r"(a) : "l"(p));
    return a;
}

__device__ __forceinline__ void cp16(uint32_t d, const void* s) {
    asm volatile("cp.async.cg.shared.global [%0], [%1], 16;" :: "r"(d), "l"(s) : "memory");
}
__device__ __forceinline__ void cp_commit() { asm volatile("cp.async.commit_group;" ::: "memory"); }
__device__ __forceinline__ void cp_wait2()  { asm volatile("cp.async.wait_group 2;" ::: "memory"); }
__device__ __forceinline__ void cp_wait1()  { asm volatile("cp.async.wait_group 1;" ::: "memory"); }
__device__ __forceinline__ void cp_wait0()  { asm volatile("cp.async.wait_group 0;" ::: "memory"); }

#define LDSM4(r, addr)                                                          \
    asm volatile("ldmatrix.sync.aligned.m8n8.x4.shared.b16 {%0,%1,%2,%3}, [%4];" \
                 : "=r"((r)[0]), "=r"((r)[1]), "=r"((r)[2]), "=r"((r)[3])        \
                 : "r"(addr))

#define MMA16816(c, a, b0, b1)                                                  \
    asm volatile("mma.sync.aligned.m16n8k16.row.col.f32.f16.f16.f32 "           \
                 "{%0,%1,%2,%3},{%4,%5,%6,%7},{%8,%9},{%0,%1,%2,%3};"           \
                 : "+f"((c)[0]), "+f"((c)[1]), "+f"((c)[2]), "+f"((c)[3])       \
                 : "r"((a)[0]), "r"((a)[1]), "r"((a)[2]), "r"((a)[3]),          \
                   "r"(b0), "r"(b1))

// ---------------------------------------------------------------------------
// Kernel 1: convert W -> fp16 directly (no fp32 staging copy)
// ---------------------------------------------------------------------------
__device__ __forceinline__ void h4_store(float4 v, __half* __restrict__ dst, size_t base) {
    __half2 p01 = __floats2half2_rn(v.x, v.y);
    __half2 p23 = __floats2half2_rn(v.z, v.w);
    uint2 u;
    u.x = *reinterpret_cast<uint32_t*>(&p01);
    u.y = *reinterpret_cast<uint32_t*>(&p23);
    *reinterpret_cast<uint2*>(dst + base) = u;
}

__global__ void convert_w_kernel(const float* __restrict__ w) {
    size_t i = (size_t)blockIdx.x * blockDim.x + threadIdx.x;
    const size_t n4 = (size_t)N_DIM * K_DIM / 4;
    if (i < n4) {
        float4 v = reinterpret_cast<const float4*>(w)[i];
        h4_store(v, g_Wh, i * 4);
    }
}

// ---------------------------------------------------------------------------
// Kernel 2: scatter shira delta into the fp16 weight (half atomics;
// duplicates accumulate, matching .at[].add semantics to fp16 precision)
// ---------------------------------------------------------------------------
__global__ void scatter_delta_kernel(const float* __restrict__ sw, const int* __restrict__ idx) {
    int i = blockIdx.x * blockDim.x + threadIdx.x;
    if (i < NNZ) {
        int r = idx[i];
        int c = idx[NNZ + i];
        atomicAdd(&g_Wh[(size_t)r * K_DIM + c], __float2half(sw[i]));
    }
}

// ---------------------------------------------------------------------------
// Kernel 3: convert x -> fp16
// ---------------------------------------------------------------------------
__global__ void convert_x_kernel(const float* __restrict__ x) {
    size_t i = (size_t)blockIdx.x * blockDim.x + threadIdx.x;
    const size_t n4 = (size_t)M_DIM * K_DIM / 4;
    if (i < n4) {
        float4 v = reinterpret_cast<const float4*>(x)[i];
        h4_store(v, g_Xh, i * 4);
    }
}

// ---------------------------------------------------------------------------
// Kernel 4: fp16 GEMM via mma.sync.m16n8k16, fragment double-buffered.
//   out[M,N] = fp16(X) * fp16(W')^T + bias  (fp32 accumulate)
// CTA 128x256, 8 warps (2x4), warp tile 64x64, BK=64, 4-stage cp.async.
// ---------------------------------------------------------------------------
extern __shared__ char dsm[];

__device__ __forceinline__ void load_stage(uint32_t st, int chunk, int tid,
                                           const char* pA, const char* pB) {
    const size_t koff = (size_t)chunk * 128;   // bytes into each K-major row
#pragma unroll
    for (int j = 0; j < 4; ++j) {              // A: 128 rows x 8 segs = 1024 ops
        int o  = j * 256 + tid;
        int r  = o >> 3;
        int sg = o & 7;
        size_t go = (size_t)r * (K_DIM * 2) + koff + (size_t)sg * 16;
        uint32_t so = (uint32_t)(r * 128) + (uint32_t)((sg * 16) ^ ((r & 7) << 4));
        cp16(st + A_OFF + so, pA + go);
    }
#pragma unroll
    for (int j = 0; j < 8; ++j) {              // B: 256 rows x 8 segs = 2048 ops
        int o  = j * 256 + tid;
        int r  = o >> 3;
        int sg = o & 7;
        size_t go = (size_t)r * (K_DIM * 2) + koff + (size_t)sg * 16;
        uint32_t so = (uint32_t)(r * 128) + (uint32_t)((sg * 16) ^ ((r & 7) << 4));
        cp16(st + B_OFF + so, pB + go);
    }
}

__global__ void __launch_bounds__(256, 1)
gemm_fp16_mma_kernel(const float* __restrict__ bias, float* __restrict__ out) {
    const int tid  = threadIdx.x;
    const int wid  = tid >> 5;
    const int lane = tid & 31;
    const int wm   = wid & 1;       // 2 M-slots of 64 rows
    const int wn   = wid >> 1;      // 4 N-slots of 64 cols

    const int m0 = blockIdx.y * BM;
    const int n0 = blockIdx.x * BN;

    uint32_t sb = (smem_u32(dsm) + 1023u) & ~1023u;

    const char* pA = (const char*)g_Xh + (size_t)m0 * (K_DIM * 2);
    const char* pB = (const char*)g_Wh + (size_t)n0 * (K_DIM * 2);

    float acc[4][8][4];
#pragma unroll
    for (int i = 0; i < 4; ++i)
#pragma unroll
        for (int j = 0; j < 8; ++j)
#pragma unroll
            for (int q = 0; q < 4; ++q) acc[i][j][q] = 0.0f;

    // Per-lane ldmatrix addressing (tile row = base + (lane&15); row&7 == lane&7,
    // so the XOR swizzle term is a per-lane constant folded into xks[]).
    const int l15 = lane & 15;
    const int lhi = lane >> 4;
    const uint32_t lsw = (uint32_t)((lane & 7) << 4);
    uint32_t xks[4];
#pragma unroll
    for (int ks = 0; ks < 4; ++ks)
        xks[ks] = (uint32_t)(ks * 32 + lhi * 16) ^ lsw;

    const uint32_t aRow = (uint32_t)((wm * 64 + l15) * 128);
    const uint32_t bRow = (uint32_t)((wn * 64 + l15) * 128);

    // Prologue: stages 0..2 in flight
    load_stage(sb, 0, tid, pA, pB);
    cp_commit();
    load_stage(sb + SSIZE, 1, tid, pA, pB);
    cp_commit();
    load_stage(sb + 2 * SSIZE, 2, tid, pA, pB);
    cp_commit();

    uint32_t aF[2][16], bF[2][16];

#define LOAD_FRAGS(buf, slot, ks)                                               \
    do {                                                                        \
        _Pragma("unroll")                                                       \
        for (int mi = 0; mi < 4; ++mi)                                          \
            LDSM4(aF[buf] + mi * 4,                                             \
                  (slot) + A_OFF + aRow + (uint32_t)(mi * 2048) + xks[ks]);     \
        _Pragma("unroll")                                                       \
        for (int nb = 0; nb < 4; ++nb)                                          \
            LDSM4(bF[buf] + nb * 4,                                             \
                  (slot) + B_OFF + bRow + (uint32_t)(nb * 2048) + xks[ks]);     \
    } while (0)

#define DO_MMAS(buf)                                                            \
    do {                                                                        \
        _Pragma("unroll")                                                       \
        for (int mi = 0; mi < 4; ++mi) {                                        \
            _Pragma("unroll")                                                   \
            for (int j = 0; j < 8; ++j) {                                       \
                const int g = j >> 1, s = j & 1;                                \
                MMA16816(acc[mi][j], aF[buf] + mi * 4,                          \
                         bF[buf][g * 4 + s], bF[buf][g * 4 + 2 + s]);           \
            }                                                                   \
        }                                                                       \
    } while (0)

    for (int kt = 0; kt < NK; ++kt) {
        const int remaining = NK - 1 - kt;     // groups after this one
        if (remaining >= 2)      cp_wait2();
        else if (remaining == 1) cp_wait1();
        else                     cp_wait0();
        __syncthreads();

        if (kt + 3 < NK) {
            load_stage(sb + ((kt + 3) & 3) * SSIZE, kt + 3, tid, pA, pB);
            cp_commit();
        }

        const uint32_t slot = sb + (kt & 3) * SSIZE;

        // Software-pipelined k-steps: LDSM(ks+1) issued before MMA(ks)
        LOAD_FRAGS(0, slot, 0);
        LOAD_FRAGS(1, slot, 1);
        DO_MMAS(0);
        LOAD_FRAGS(0, slot, 2);
        DO_MMAS(1);
        LOAD_FRAGS(1, slot, 3);
        DO_MMAS(0);
        DO_MMAS(1);
    }

    // Epilogue: C frag (m16n8): c0,c1 at (m = l>>2, n = 2*(l&3)); c2,c3 at m+8.
    const int mBase = m0 + wm * 64;
    const int nBase = n0 + wn * 64;
    const int rsub  = lane >> 2;
    const int csub  = (lane & 3) * 2;
#pragma unroll
    for (int j = 0; j < 8; ++j) {
        const int n = nBase + j * 8 + csub;
        const float2 b2 = *reinterpret_cast<const float2*>(bias + n);
#pragma unroll
        for (int mi = 0; mi < 4; ++mi) {
            const int r0 = mBase + mi * 16 + rsub;
            float2 v0, v1;
            v0.x = acc[mi][j][0] + b2.x;
            v0.y = acc[mi][j][1] + b2.y;
            v1.x = acc[mi][j][2] + b2.x;
            v1.y = acc[mi][j][3] + b2.y;
            *reinterpret_cast<float2*>(out + (size_t)r0 * N_DIM + n)       = v0;
            *reinterpret_cast<float2*>(out + (size_t)(r0 + 8) * N_DIM + n) = v1;
        }
    }
}

// ---------------------------------------------------------------------------
// Entry point
// ---------------------------------------------------------------------------
extern "C" void kernel_launch(void* const* d_in, const int* in_sizes, int n_in,
                              void* d_out, int out_size) {
    const float* x    = (const float*)d_in[0];   // [4, 2048, 4096]
    const float* w    = (const float*)d_in[1];   // [4096, 4096]
    const float* bias = (const float*)d_in[2];   // [4096]
    const float* sw   = (const float*)d_in[3];   // [262144]
    const int*   idx  = (const int*)d_in[4];     // [2, 262144]
    float* out = (float*)d_out;                  // [8192, 4096]

    {
        const size_t n4 = (size_t)N_DIM * K_DIM / 4;
        convert_w_kernel<<<(int)((n4 + 255) / 256), 256>>>(w);
    }
    scatter_delta_kernel<<<(NNZ + 255) / 256, 256>>>(sw, idx);
    {
        const size_t n4 = (size_t)M_DIM * K_DIM / 4;
        convert_x_kernel<<<(int)((n4 + 255) / 256), 256>>>(x);
    }
    {
        cudaFuncSetAttribute(gemm_fp16_mma_kernel,
                             cudaFuncAttributeMaxDynamicSharedMemorySize, DSMEM_BYTES);
        dim3 grid(N_DIM / BN, M_DIM / BM);   // (16, 64)
        gemm_fp16_mma_kernel<<<grid, 256, DSMEM_BYTES>>>(bias, out);
    }
}